// round 16
// baseline (speedup 1.0000x reference)
#include <cuda_runtime.h>
#include <cuda_fp16.h>
#include <math.h>
#include <stdint.h>

#define TOKENS 8192
#define DMODEL 768
#define HEADS  12
#define DHEAD  64
#define DFF    3072
#define DEPTH  12
#define SEQ    1024
#define QKV3   2304   // 3 * 768

// ---------------- scratch (allocation-free: __device__ globals) ----------------
__device__ float  g_x[TOKENS * DMODEL];          // residual stream (fp32)
__device__ __half g_h[TOKENS * DMODEL];          // post-LN activations (fp16)
__device__ __half g_qkv[TOKENS * QKV3];          // fused qkv (fp16)
__device__ __half g_attnout[TOKENS * DMODEL];    // attention output (fp16)
__device__ __half g_ff[TOKENS * DFF];            // FF hidden (fp16)

// pre-transposed fp16 weights: [layer][N][K]
__device__ __half g_wqkvT[DEPTH * QKV3 * DMODEL];
__device__ __half g_woT[DEPTH * DMODEL * DMODEL];
__device__ __half g_w1T[DEPTH * DFF * DMODEL];
__device__ __half g_w2T[DEPTH * DMODEL * DFF];

// ---------------- helpers ----------------
__device__ __forceinline__ uint32_t smem_u32(const void* p) {
    uint32_t a;
    asm("{ .reg .u64 t; cvta.to.shared.u64 t, %1; cvt.u32.u64 %0, t; }" : "=r"(a) : "l"(p));
    return a;
}
__device__ __forceinline__ void cp_async16(uint32_t dst, const void* src) {
    asm volatile("cp.async.cg.shared.global [%0], [%1], 16;" :: "r"(dst), "l"(src));
}
#define CP_COMMIT() asm volatile("cp.async.commit_group;" ::: "memory")
#define CP_WAIT0()  asm volatile("cp.async.wait_group 0;" ::: "memory")

__device__ __forceinline__ void mma_f16_16x8x16(float* d, const uint32_t* a,
                                                uint32_t b0, uint32_t b1) {
    asm volatile(
        "mma.sync.aligned.m16n8k16.row.col.f32.f16.f16.f32 "
        "{%0,%1,%2,%3}, {%4,%5,%6,%7}, {%8,%9}, {%0,%1,%2,%3};\n"
        : "+f"(d[0]), "+f"(d[1]), "+f"(d[2]), "+f"(d[3])
        : "r"(a[0]), "r"(a[1]), "r"(a[2]), "r"(a[3]), "r"(b0), "r"(b1));
}
__device__ __forceinline__ uint32_t packh2(float x, float y) {
    __half2 t = __floats2half2_rn(x, y);
    return *(uint32_t*)&t;
}

// ---------------- weight transpose: W[K][N] f32 -> WT[N][K] fp16 ----------------
__global__ __launch_bounds__(256) void wtrans_kernel(
    const float* __restrict__ W, __half* __restrict__ WT, int K, int N)
{
    __shared__ float T[32][33];
    int l = blockIdx.z;
    const float* Wl = W + (size_t)l * K * N;
    __half* Hl = WT + (size_t)l * K * N;
    int k0 = blockIdx.x * 32, n0 = blockIdx.y * 32;
    int tx = threadIdx.x & 31, ty = threadIdx.x >> 5;
    #pragma unroll
    for (int i = 0; i < 4; i++)
        T[ty + 8 * i][tx] = Wl[(size_t)(k0 + ty + 8 * i) * N + n0 + tx];
    __syncthreads();
    #pragma unroll
    for (int i = 0; i < 4; i++) {
        int n = n0 + ty + 8 * i, k = k0 + tx;
        Hl[(size_t)n * K + k] = __float2half(T[tx][ty + 8 * i]);
    }
}

// ---------------- cp.async pipelined fp16 GEMM ----------------
// Block tile BM x 128 (BM = 128 or 64). 256 threads = 8 warps.
// BM=128: 4m x 2n warps, warp tile 32x64 (R14-validated).
// BM=64:  2m x 4n warps, warp tile 32x32; smem 30KB + ~85 regs -> 3 blocks/SM
//         (tail-wave fix for the N=768 GEMMs). launch_bounds minBlocks=2 only
//         (cap 128 regs; NO spill — the R15 BN=64/minBlocks=3 mistake).
// Per-output k-accumulation order identical in both variants.
template <int EPI, int OUTH, int BM>
__global__ __launch_bounds__(256, (BM == 64) ? 2 : 1) void gemm_fp16_kernel(
    const __half* __restrict__ A, const __half* __restrict__ BT,
    const float* __restrict__ bias, const float* __restrict__ res,
    void* __restrict__ Cout, int M, int N, int K)
{
    constexpr int MW  = (BM == 128) ? 4 : 2;   // m-warps
    constexpr int NW  = 8 / MW;                // n-warps
    constexpr int NWW = 128 / NW;              // warp n-width
    constexpr int NTI = NWW / 8;               // n-tiles per warp
    constexpr int ASTAGE_B = BM * 80;
    constexpr int BSTAGE_B = 128 * 80;

    __shared__ __half As[2][BM * 40];
    __shared__ __half Bs[2][128 * 40];

    int tid  = threadIdx.x;
    int lane = tid & 31;
    int wid  = tid >> 5;
    int wm = wid & (MW - 1), wn = wid / MW;
    int bm = blockIdx.y * BM, bn = blockIdx.x * 128;
    int grp = lane >> 2, thr = lane & 3;

    float acc[2][NTI][4];
    #pragma unroll
    for (int i = 0; i < 2; i++)
        #pragma unroll
        for (int j = 0; j < NTI; j++)
            #pragma unroll
            for (int v = 0; v < 4; v++) acc[i][j][v] = 0.f;

    // A staging
    const __half* agp;
    uint32_t sA;
    if (BM == 128) {
        agp = A + (size_t)(bm + (tid >> 1)) * K + (tid & 1) * 16;
        sA  = smem_u32(As) + (tid >> 1) * 80 + (tid & 1) * 32;
    } else {
        agp = A + (size_t)(bm + (tid >> 2)) * K + (tid & 3) * 8;
        sA  = smem_u32(As) + (tid >> 2) * 80 + (tid & 3) * 16;
    }
    // B staging (identical both variants)
    const __half* bgp = BT + (size_t)(bn + (tid >> 1)) * K + (tid & 1) * 16;
    uint32_t sB = smem_u32(Bs) + (tid >> 1) * 80 + (tid & 1) * 32;

    int ktiles = K / 32;
    // prologue: tile 0 -> stage 0
    if (BM == 128) { cp_async16(sA, agp);  cp_async16(sA + 16, agp + 8); }
    else           { cp_async16(sA, agp); }
    cp_async16(sB, bgp);  cp_async16(sB + 16, bgp + 8);
    CP_COMMIT();

    for (int c = 0; c < ktiles; c++) {
        CP_WAIT0();
        __syncthreads();

        if (c + 1 < ktiles) {
            int s = (c + 1) & 1;
            int kc = (c + 1) * 32;
            if (BM == 128) {
                cp_async16(sA + s * ASTAGE_B, agp + kc);
                cp_async16(sA + s * ASTAGE_B + 16, agp + kc + 8);
            } else {
                cp_async16(sA + s * ASTAGE_B, agp + kc);
            }
            cp_async16(sB + s * BSTAGE_B, bgp + kc);
            cp_async16(sB + s * BSTAGE_B + 16, bgp + kc + 8);
            CP_COMMIT();
        }

        const __half* Ab = As[c & 1];
        const __half* Bb = Bs[c & 1];
        #pragma unroll
        for (int s2 = 0; s2 < 2; s2++) {
            int kb = s2 * 16;
            uint32_t af[2][4];
            #pragma unroll
            for (int mt = 0; mt < 2; mt++) {
                int r = wm * 32 + mt * 16 + grp;
                af[mt][0] = *(const uint32_t*)&Ab[ r      * 40 + kb + 2 * thr    ];
                af[mt][1] = *(const uint32_t*)&Ab[(r + 8) * 40 + kb + 2 * thr    ];
                af[mt][2] = *(const uint32_t*)&Ab[ r      * 40 + kb + 2 * thr + 8];
                af[mt][3] = *(const uint32_t*)&Ab[(r + 8) * 40 + kb + 2 * thr + 8];
            }
            #pragma unroll
            for (int nt = 0; nt < NTI; nt++) {
                int c2 = wn * NWW + nt * 8 + grp;
                uint32_t b0 = *(const uint32_t*)&Bb[c2 * 40 + kb + 2 * thr    ];
                uint32_t b1 = *(const uint32_t*)&Bb[c2 * 40 + kb + 2 * thr + 8];
                #pragma unroll
                for (int mt = 0; mt < 2; mt++)
                    mma_f16_16x8x16(acc[mt][nt], af[mt], b0, b1);
            }
        }
    }

    #pragma unroll
    for (int mt = 0; mt < 2; mt++) {
        #pragma unroll
        for (int nt = 0; nt < NTI; nt++) {
            int r0 = bm + wm * 32 + mt * 16 + grp;
            int c0 = bn + wn * NWW + nt * 8 + 2 * thr;
            #pragma unroll
            for (int hh = 0; hh < 2; hh++) {
                int m = r0 + hh * 8;
                float v0 = acc[mt][nt][hh * 2 + 0];
                float v1 = acc[mt][nt][hh * 2 + 1];
                if (EPI >= 1) { v0 += bias[c0]; v1 += bias[c0 + 1]; }
                if (EPI == 2) {
                    v0 = 0.5f * v0 * (1.0f + erff(v0 * 0.70710678118654752f));
                    v1 = 0.5f * v1 * (1.0f + erff(v1 * 0.70710678118654752f));
                }
                if (EPI == 1) {
                    const float* rr = res + (size_t)m * N + c0;
                    v0 += rr[0]; v1 += rr[1];
                }
                if (OUTH) {
                    *(uint32_t*)((__half*)Cout + (size_t)m * N + c0) = packh2(v0, v1);
                } else {
                    *(float2*)((float*)Cout + (size_t)m * N + c0) = make_float2(v0, v1);
                }
            }
        }
    }
}

// ---------------- utility ----------------
__global__ void copy4_kernel(const float4* __restrict__ src, float4* __restrict__ dst, int n) {
    int i = blockIdx.x * blockDim.x + threadIdx.x;
    if (i < n) dst[i] = src[i];
}

// ---------------- LayerNorm: warp per 2 rows ----------------
template <int OUTH>
__global__ __launch_bounds__(256) void ln_kernel(
    const float* __restrict__ in, const float* __restrict__ w,
    const float* __restrict__ b, void* __restrict__ out)
{
    int warp = threadIdx.x >> 5, lane = threadIdx.x & 31;
    int row0 = blockIdx.x * 16 + warp * 2;
    const float4* pa = (const float4*)(in + (size_t)row0 * DMODEL);
    const float4* pb = (const float4*)(in + (size_t)(row0 + 1) * DMODEL);

    float4 va[6], vb[6];
    float sa = 0.f, qa = 0.f, sb = 0.f, qb = 0.f;
    #pragma unroll
    for (int i = 0; i < 6; i++) {
        va[i] = pa[lane + i * 32];
        vb[i] = pb[lane + i * 32];
        sa += va[i].x + va[i].y + va[i].z + va[i].w;
        qa += va[i].x * va[i].x + va[i].y * va[i].y + va[i].z * va[i].z + va[i].w * va[i].w;
        sb += vb[i].x + vb[i].y + vb[i].z + vb[i].w;
        qb += vb[i].x * vb[i].x + vb[i].y * vb[i].y + vb[i].z * vb[i].z + vb[i].w * vb[i].w;
    }
    #pragma unroll
    for (int o = 16; o > 0; o >>= 1) {
        sa += __shfl_xor_sync(0xffffffffu, sa, o);
        qa += __shfl_xor_sync(0xffffffffu, qa, o);
        sb += __shfl_xor_sync(0xffffffffu, sb, o);
        qb += __shfl_xor_sync(0xffffffffu, qb, o);
    }
    float mua = sa * (1.0f / DMODEL), mub = sb * (1.0f / DMODEL);
    float rsa = rsqrtf(qa * (1.0f / DMODEL) - mua * mua + 1e-5f);
    float rsb = rsqrtf(qb * (1.0f / DMODEL) - mub * mub + 1e-5f);

    #pragma unroll
    for (int i = 0; i < 6; i++) {
        int c = (lane + i * 32) * 4;
        float4 wv = *(const float4*)(w + c);
        float4 bv = *(const float4*)(b + c);
        float4 ra, rb;
        ra.x = (va[i].x - mua) * rsa * wv.x + bv.x;
        ra.y = (va[i].y - mua) * rsa * wv.y + bv.y;
        ra.z = (va[i].z - mua) * rsa * wv.z + bv.z;
        ra.w = (va[i].w - mua) * rsa * wv.w + bv.w;
        rb.x = (vb[i].x - mub) * rsb * wv.x + bv.x;
        rb.y = (vb[i].y - mub) * rsb * wv.y + bv.y;
        rb.z = (vb[i].z - mub) * rsb * wv.z + bv.z;
        rb.w = (vb[i].w - mub) * rsb * wv.w + bv.w;
        if (OUTH) {
            ((uint2*)((__half*)out + (size_t)row0 * DMODEL))[lane + i * 32] =
                make_uint2(packh2(ra.x, ra.y), packh2(ra.z, ra.w));
            ((uint2*)((__half*)out + (size_t)(row0 + 1) * DMODEL))[lane + i * 32] =
                make_uint2(packh2(rb.x, rb.y), packh2(rb.z, rb.w));
        } else {
            ((float4*)((float*)out + (size_t)row0 * DMODEL))[lane + i * 32] = ra;
            ((float4*)((float*)out + (size_t)(row0 + 1) * DMODEL))[lane + i * 32] = rb;
        }
    }
}

// ---------------- fp16 tensor-core flash attention (R14, unchanged) ----------------
__global__ __launch_bounds__(256, 2) void attn_fp16_kernel(
    const __half* __restrict__ qkv, __half* __restrict__ out)
{
    __shared__ __half sm[18432];
    __half* Qs = sm;                     // [128][72] (staging only)
    __half* Ks = sm;                     // [64][72]
    __half* Vt = sm + 4608;              // [64][72]  transposed V: Vt[d][kk]
    __half* Ps = sm + 9216;              // [128][72]

    int tid = threadIdx.x;
    int lane = tid & 31, wid = tid >> 5;
    int grp = lane >> 2, thr = lane & 3;

    int bh = blockIdx.y;
    int b = bh / HEADS, h = bh % HEADS;
    int qt = blockIdx.x * 128;

    const __half* qbase = qkv + (size_t)(b * SEQ) * QKV3 + h * DHEAD;
    const __half* kbase = qbase + DMODEL;
    const __half* vbase = qbase + 2 * DMODEL;

    int lr = tid >> 3, lc8 = (tid & 7) * 8;
    int rot0 = tid & 7, rot1 = (tid + 256) & 7;

    uint4 kreg[2], vreg[2];
    kreg[0] = *(const uint4*)(kbase + (size_t)lr * QKV3 + lc8);
    kreg[1] = *(const uint4*)(kbase + (size_t)(lr + 32) * QKV3 + lc8);
    vreg[0] = *(const uint4*)(vbase + (size_t)lr * QKV3 + lc8);
    vreg[1] = *(const uint4*)(vbase + (size_t)(lr + 32) * QKV3 + lc8);

    {
        const __half2 s2 = __floats2half2_rn(0.125f, 0.125f);
        #pragma unroll
        for (int v = 0; v < 4; v++) {
            int idx = tid + v * 256;
            int r = idx >> 3, c8 = (idx & 7) * 8;
            uint4 q4 = *(const uint4*)(qbase + (size_t)(qt + r) * QKV3 + c8);
            __half2* hp = (__half2*)&q4;
            #pragma unroll
            for (int j = 0; j < 4; j++) hp[j] = __hmul2(hp[j], s2);
            *(uint4*)&Qs[r * 72 + c8] = q4;
        }
    }
    __syncthreads();

    uint32_t qfrag[4][4];
    int qr = wid * 16 + grp;
    #pragma unroll
    for (int ks = 0; ks < 4; ks++) {
        qfrag[ks][0] = *(const uint32_t*)&Qs[ qr      * 72 + ks * 16 + 2 * thr    ];
        qfrag[ks][1] = *(const uint32_t*)&Qs[(qr + 8) * 72 + ks * 16 + 2 * thr    ];
        qfrag[ks][2] = *(const uint32_t*)&Qs[ qr      * 72 + ks * 16 + 2 * thr + 8];
        qfrag[ks][3] = *(const uint32_t*)&Qs[(qr + 8) * 72 + ks * 16 + 2 * thr + 8];
    }
    __syncthreads();

    float acc_o[8][4];
    #pragma unroll
    for (int nt = 0; nt < 8; nt++)
        #pragma unroll
        for (int v = 0; v < 4; v++) acc_o[nt][v] = 0.f;
    float m0 = -1e30f, m1 = -1e30f, l0 = 0.f, l1 = 0.f;

    for (int kt0 = 0; kt0 < SEQ; kt0 += 64) {
        {
            *(uint4*)&Ks[lr * 72 + lc8] = kreg[0];
            *(uint4*)&Ks[(lr + 32) * 72 + lc8] = kreg[1];
            const __half* vh0 = (const __half*)&vreg[0];
            const __half* vh1 = (const __half*)&vreg[1];
            #pragma unroll
            for (int j = 0; j < 8; j++) {
                int j0 = (j + rot0) & 7;
                Vt[(lc8 + j0) * 72 + lr] = vh0[j0];
                int j1 = (j + rot1) & 7;
                Vt[(lc8 + j1) * 72 + lr + 32] = vh1[j1];
            }
        }
        __syncthreads();

        if (kt0 + 64 < SEQ) {
            const __half* kp = kbase + (size_t)(kt0 + 64) * QKV3;
            const __half* vp = vbase + (size_t)(kt0 + 64) * QKV3;
            kreg[0] = *(const uint4*)(kp + (size_t)lr * QKV3 + lc8);
            kreg[1] = *(const uint4*)(kp + (size_t)(lr + 32) * QKV3 + lc8);
            vreg[0] = *(const uint4*)(vp + (size_t)lr * QKV3 + lc8);
            vreg[1] = *(const uint4*)(vp + (size_t)(lr + 32) * QKV3 + lc8);
        }

        float acc_s[8][4];
        #pragma unroll
        for (int nt = 0; nt < 8; nt++)
            #pragma unroll
            for (int v = 0; v < 4; v++) acc_s[nt][v] = 0.f;

        #pragma unroll
        for (int ks = 0; ks < 4; ks++) {
            #pragma unroll
            for (int nt = 0; nt < 8; nt++) {
                int c = nt * 8 + grp;
                uint32_t b0 = *(const uint32_t*)&Ks[c * 72 + ks * 16 + 2 * thr    ];
                uint32_t b1 = *(const uint32_t*)&Ks[c * 72 + ks * 16 + 2 * thr + 8];
                mma_f16_16x8x16(acc_s[nt], qfrag[ks], b0, b1);
            }
        }

        float tm0 = -1e30f, tm1 = -1e30f;
        #pragma unroll
        for (int nt = 0; nt < 8; nt++) {
            tm0 = fmaxf(tm0, fmaxf(acc_s[nt][0], acc_s[nt][1]));
            tm1 = fmaxf(tm1, fmaxf(acc_s[nt][2], acc_s[nt][3]));
        }
        tm0 = fmaxf(tm0, __shfl_xor_sync(0xffffffffu, tm0, 1));
        tm0 = fmaxf(tm0, __shfl_xor_sync(0xffffffffu, tm0, 2));
        tm1 = fmaxf(tm1, __shfl_xor_sync(0xffffffffu, tm1, 1));
        tm1 = fmaxf(tm1, __shfl_xor_sync(0xffffffffu, tm1, 2));

        float nm0 = fmaxf(m0, tm0), nm1 = fmaxf(m1, tm1);
        float c0 = __expf(m0 - nm0),  c1 = __expf(m1 - nm1);

        float s0 = 0.f, s1 = 0.f;
        #pragma unroll
        for (int nt = 0; nt < 8; nt++) {
            acc_s[nt][0] = __expf(acc_s[nt][0] - nm0);
            acc_s[nt][1] = __expf(acc_s[nt][1] - nm0);
            acc_s[nt][2] = __expf(acc_s[nt][2] - nm1);
            acc_s[nt][3] = __expf(acc_s[nt][3] - nm1);
            s0 += acc_s[nt][0] + acc_s[nt][1];
            s1 += acc_s[nt][2] + acc_s[nt][3];
        }
        s0 += __shfl_xor_sync(0xffffffffu, s0, 1);
        s0 += __shfl_xor_sync(0xffffffffu, s0, 2);
        s1 += __shfl_xor_sync(0xffffffffu, s1, 1);
        s1 += __shfl_xor_sync(0xffffffffu, s1, 2);

        l0 = l0 * c0 + s0;  l1 = l1 * c1 + s1;
        m0 = nm0;           m1 = nm1;

        #pragma unroll
        for (int nt = 0; nt < 8; nt++) {
            acc_o[nt][0] *= c0; acc_o[nt][1] *= c0;
            acc_o[nt][2] *= c1; acc_o[nt][3] *= c1;
        }

        #pragma unroll
        for (int nt = 0; nt < 8; nt++) {
            *(uint32_t*)&Ps[ qr      * 72 + nt * 8 + 2 * thr] = packh2(acc_s[nt][0], acc_s[nt][1]);
            *(uint32_t*)&Ps[(qr + 8) * 72 + nt * 8 + 2 * thr] = packh2(acc_s[nt][2], acc_s[nt][3]);
        }
        __syncwarp();

        #pragma unroll
        for (int ks2 = 0; ks2 < 4; ks2++) {
            uint32_t af[4];
            af[0] = *(const uint32_t*)&Ps[ qr      * 72 + ks2 * 16 + 2 * thr    ];
            af[1] = *(const uint32_t*)&Ps[(qr + 8) * 72 + ks2 * 16 + 2 * thr    ];
            af[2] = *(const uint32_t*)&Ps[ qr      * 72 + ks2 * 16 + 2 * thr + 8];
            af[3] = *(const uint32_t*)&Ps[(qr + 8) * 72 + ks2 * 16 + 2 * thr + 8];
            #pragma unroll
            for (int nt = 0; nt < 8; nt++) {
                int d = nt * 8 + grp;
                uint32_t b0 = *(const uint32_t*)&Vt[d * 72 + ks2 * 16 + 2 * thr    ];
                uint32_t b1 = *(const uint32_t*)&Vt[d * 72 + ks2 * 16 + 2 * thr + 8];
                mma_f16_16x8x16(acc_o[nt], af, b0, b1);
            }
        }
        __syncthreads();
    }

    float il0 = 1.0f / l0, il1 = 1.0f / l1;
    int tok0 = b * SEQ + qt + wid * 16 + grp;
    #pragma unroll
    for (int nt = 0; nt < 8; nt++) {
        int col = h * DHEAD + nt * 8 + 2 * thr;
        *(uint32_t*)(out + (size_t)tok0 * DMODEL + col) =
            packh2(acc_o[nt][0] * il0, acc_o[nt][1] * il0);
        *(uint32_t*)(out + (size_t)(tok0 + 8) * DMODEL + col) =
            packh2(acc_o[nt][2] * il1, acc_o[nt][3] * il1);
    }
}

// ---------------- host orchestration ----------------
extern "C" void kernel_launch(void* const* d_in, const int* in_sizes, int n_in,
                              void* d_out, int out_size)
{
    const float* x     = (const float*)d_in[0];
    const float* ln1w  = (const float*)d_in[1];
    const float* ln1b  = (const float*)d_in[2];
    const float* wqkv  = (const float*)d_in[3];
    const float* wo    = (const float*)d_in[4];
    const float* bo    = (const float*)d_in[5];
    const float* ln2w  = (const float*)d_in[6];
    const float* ln2b  = (const float*)d_in[7];
    const float* w1    = (const float*)d_in[8];
    const float* b1    = (const float*)d_in[9];
    const float* w2    = (const float*)d_in[10];
    const float* b2    = (const float*)d_in[11];
    const float* lnfw  = (const float*)d_in[12];
    const float* lnfb  = (const float*)d_in[13];

    float *gx;
    __half *gh, *gqkv, *gao, *gff;
    cudaGetSymbolAddress((void**)&gx,   g_x);
    cudaGetSymbolAddress((void**)&gh,   g_h);
    cudaGetSymbolAddress((void**)&gqkv, g_qkv);
    cudaGetSymbolAddress((void**)&gao,  g_attnout);
    cudaGetSymbolAddress((void**)&gff,  g_ff);

    __half *qkvT, *woT, *w1T, *w2T;
    cudaGetSymbolAddress((void**)&qkvT, g_wqkvT);
    cudaGetSymbolAddress((void**)&woT,  g_woT);
    cudaGetSymbolAddress((void**)&w1T,  g_w1T);
    cudaGetSymbolAddress((void**)&w2T,  g_w2T);

    // ---- weight transpose prepass ----
    wtrans_kernel<<<dim3(DMODEL / 32, QKV3 / 32, DEPTH), 256>>>(wqkv, qkvT, DMODEL, QKV3);
    wtrans_kernel<<<dim3(DMODEL / 32, DMODEL / 32, DEPTH), 256>>>(wo, woT, DMODEL, DMODEL);
    wtrans_kernel<<<dim3(DMODEL / 32, DFF / 32, DEPTH), 256>>>(w1, w1T, DMODEL, DFF);
    wtrans_kernel<<<dim3(DFF / 32, DMODEL / 32, DEPTH), 256>>>(w2, w2T, DFF, DMODEL);

    {
        int n4 = TOKENS * DMODEL / 4;
        copy4_kernel<<<(n4 + 255) / 256, 256>>>((const float4*)x, (float4*)gx, n4);
    }

    for (int l = 0; l < DEPTH; l++) {
        const float* L1w = ln1w + (size_t)l * DMODEL;
        const float* L1b = ln1b + (size_t)l * DMODEL;
        const float* Bo  = bo   + (size_t)l * DMODEL;
        const float* L2w = ln2w + (size_t)l * DMODEL;
        const float* L2b = ln2b + (size_t)l * DMODEL;
        const float* B1  = b1   + (size_t)l * DFF;
        const float* B2  = b2   + (size_t)l * DMODEL;

        const __half* Wq = qkvT + (size_t)l * QKV3 * DMODEL;
        const __half* Wo = woT  + (size_t)l * DMODEL * DMODEL;
        const __half* W1 = w1T  + (size_t)l * DFF * DMODEL;
        const __half* W2 = w2T  + (size_t)l * DMODEL * DFF;

        ln_kernel<1><<<TOKENS / 16, 256>>>(gx, L1w, L1b, gh);
        // QKV: BM=128 (R14-validated config)
        gemm_fp16_kernel<0, 1, 128><<<dim3(QKV3 / 128, TOKENS / 128), 256>>>(
            gh, Wq, nullptr, nullptr, gqkv, TOKENS, QKV3, DMODEL);
        attn_fp16_kernel<<<dim3(SEQ / 128, 8 * HEADS), 256>>>(gqkv, gao);
        // O-proj: N=768 -> BM=64 (tail-wave fix, no reg cap below natural usage)
        gemm_fp16_kernel<1, 0, 64><<<dim3(DMODEL / 128, TOKENS / 64), 256>>>(
            gao, Wo, Bo, gx, gx, TOKENS, DMODEL, DMODEL);
        ln_kernel<1><<<TOKENS / 16, 256>>>(gx, L2w, L2b, gh);
        // FF1: BM=128
        gemm_fp16_kernel<2, 1, 128><<<dim3(DFF / 128, TOKENS / 128), 256>>>(
            gh, W1, B1, nullptr, gff, TOKENS, DFF, DMODEL);
        // FF2: N=768, K=3072 -> BM=64
        gemm_fp16_kernel<1, 0, 64><<<dim3(DMODEL / 128, TOKENS / 64), 256>>>(
            gff, W2, B2, gx, gx, TOKENS, DMODEL, DFF);
    }

    ln_kernel<0><<<TOKENS / 16, 256>>>(gx, lnfw, lnfb, (float*)d_out);
}

// round 17
// speedup vs baseline: 1.1462x; 1.1462x over previous
#include <cuda_runtime.h>
#include <cuda_fp16.h>
#include <math.h>
#include <stdint.h>

#define TOKENS 8192
#define DMODEL 768
#define HEADS  12
#define DHEAD  64
#define DFF    3072
#define DEPTH  12
#define SEQ    1024
#define QKV3   2304   // 3 * 768

// ---------------- scratch (allocation-free: __device__ globals) ----------------
__device__ float  g_x[TOKENS * DMODEL];          // residual stream (fp32)
__device__ __half g_h[TOKENS * DMODEL];          // post-LN activations (fp16)
__device__ __half g_qkv[TOKENS * QKV3];          // fused qkv (fp16)
__device__ __half g_attnout[TOKENS * DMODEL];    // attention output (fp16)
__device__ __half g_ff[TOKENS * DFF];            // FF hidden (fp16)

// pre-transposed fp16 weights: [layer][N][K]
__device__ __half g_wqkvT[DEPTH * QKV3 * DMODEL];
__device__ __half g_woT[DEPTH * DMODEL * DMODEL];
__device__ __half g_w1T[DEPTH * DFF * DMODEL];
__device__ __half g_w2T[DEPTH * DMODEL * DFF];

// ---------------- helpers ----------------
__device__ __forceinline__ uint32_t smem_u32(const void* p) {
    uint32_t a;
    asm("{ .reg .u64 t; cvta.to.shared.u64 t, %1; cvt.u32.u64 %0, t; }" : "=r"(a) : "l"(p));
    return a;
}
__device__ __forceinline__ void cp_async16(uint32_t dst, const void* src) {
    asm volatile("cp.async.cg.shared.global [%0], [%1], 16;" :: "r"(dst), "l"(src));
}
#define CP_COMMIT() asm volatile("cp.async.commit_group;" ::: "memory")
#define CP_WAIT0()  asm volatile("cp.async.wait_group 0;" ::: "memory")

__device__ __forceinline__ void mma_f16_16x8x16(float* d, const uint32_t* a,
                                                uint32_t b0, uint32_t b1) {
    asm volatile(
        "mma.sync.aligned.m16n8k16.row.col.f32.f16.f16.f32 "
        "{%0,%1,%2,%3}, {%4,%5,%6,%7}, {%8,%9}, {%0,%1,%2,%3};\n"
        : "+f"(d[0]), "+f"(d[1]), "+f"(d[2]), "+f"(d[3])
        : "r"(a[0]), "r"(a[1]), "r"(a[2]), "r"(a[3]), "r"(b0), "r"(b1));
}
__device__ __forceinline__ uint32_t packh2(float x, float y) {
    __half2 t = __floats2half2_rn(x, y);
    return *(uint32_t*)&t;
}

// ---------------- weight transpose: W[K][N] f32 -> WT[N][K] fp16 ----------------
__global__ __launch_bounds__(256) void wtrans_kernel(
    const float* __restrict__ W, __half* __restrict__ WT, int K, int N)
{
    __shared__ float T[32][33];
    int l = blockIdx.z;
    const float* Wl = W + (size_t)l * K * N;
    __half* Hl = WT + (size_t)l * K * N;
    int k0 = blockIdx.x * 32, n0 = blockIdx.y * 32;
    int tx = threadIdx.x & 31, ty = threadIdx.x >> 5;
    #pragma unroll
    for (int i = 0; i < 4; i++)
        T[ty + 8 * i][tx] = Wl[(size_t)(k0 + ty + 8 * i) * N + n0 + tx];
    __syncthreads();
    #pragma unroll
    for (int i = 0; i < 4; i++) {
        int n = n0 + ty + 8 * i, k = k0 + tx;
        Hl[(size_t)n * K + k] = __float2half(T[tx][ty + 8 * i]);
    }
}

// ---------------- cp.async pipelined fp16 GEMM, single barrier per k-tile ----------------
// R14-validated: 128x128 tile, 8 warps (4m x 2n), warp tile 32x64, BK=32,
// 2-stage cp.async, wait(c) -> sync -> issue(c+1) -> compute(c).
#define GK_STAGE_B 10240   // 128*40*2 bytes

template <int EPI, int OUTH>
__global__ __launch_bounds__(256) void gemm_fp16_kernel(
    const __half* __restrict__ A, const __half* __restrict__ BT,
    const float* __restrict__ bias, const float* __restrict__ res,
    void* __restrict__ Cout, int M, int N, int K)
{
    __shared__ __half As[2][128 * 40];
    __shared__ __half Bs[2][128 * 40];

    int tid  = threadIdx.x;
    int lane = tid & 31;
    int wid  = tid >> 5;
    int wm = wid & 3, wn = wid >> 2;
    int bm = blockIdx.y * 128, bn = blockIdx.x * 128;
    int grp = lane >> 2, thr = lane & 3;

    float acc[2][8][4];
    #pragma unroll
    for (int i = 0; i < 2; i++)
        #pragma unroll
        for (int j = 0; j < 8; j++)
            #pragma unroll
            for (int v = 0; v < 4; v++) acc[i][j][v] = 0.f;

    int ar = tid >> 1;
    const __half* agp = A  + (size_t)(bm + ar) * K + (tid & 1) * 16;
    const __half* bgp = BT + (size_t)(bn + ar) * K + (tid & 1) * 16;
    uint32_t sA = smem_u32(As) + ar * 80 + (tid & 1) * 32;
    uint32_t sB = smem_u32(Bs) + ar * 80 + (tid & 1) * 32;

    int ktiles = K / 32;
    cp_async16(sA, agp);  cp_async16(sA + 16, agp + 8);
    cp_async16(sB, bgp);  cp_async16(sB + 16, bgp + 8);
    CP_COMMIT();

    for (int c = 0; c < ktiles; c++) {
        CP_WAIT0();
        __syncthreads();

        if (c + 1 < ktiles) {
            int s = (c + 1) & 1;
            int kc = (c + 1) * 32;
            cp_async16(sA + s * GK_STAGE_B, agp + kc);
            cp_async16(sA + s * GK_STAGE_B + 16, agp + kc + 8);
            cp_async16(sB + s * GK_STAGE_B, bgp + kc);
            cp_async16(sB + s * GK_STAGE_B + 16, bgp + kc + 8);
            CP_COMMIT();
        }

        const __half* Ab = As[c & 1];
        const __half* Bb = Bs[c & 1];
        #pragma unroll
        for (int s2 = 0; s2 < 2; s2++) {
            int kb = s2 * 16;
            uint32_t af[2][4];
            #pragma unroll
            for (int mt = 0; mt < 2; mt++) {
                int r = wm * 32 + mt * 16 + grp;
                af[mt][0] = *(const uint32_t*)&Ab[ r      * 40 + kb + 2 * thr    ];
                af[mt][1] = *(const uint32_t*)&Ab[(r + 8) * 40 + kb + 2 * thr    ];
                af[mt][2] = *(const uint32_t*)&Ab[ r      * 40 + kb + 2 * thr + 8];
                af[mt][3] = *(const uint32_t*)&Ab[(r + 8) * 40 + kb + 2 * thr + 8];
            }
            #pragma unroll
            for (int nt = 0; nt < 8; nt++) {
                int c2 = wn * 64 + nt * 8 + grp;
                uint32_t b0 = *(const uint32_t*)&Bb[c2 * 40 + kb + 2 * thr    ];
                uint32_t b1 = *(const uint32_t*)&Bb[c2 * 40 + kb + 2 * thr + 8];
                #pragma unroll
                for (int mt = 0; mt < 2; mt++)
                    mma_f16_16x8x16(acc[mt][nt], af[mt], b0, b1);
            }
        }
    }

    #pragma unroll
    for (int mt = 0; mt < 2; mt++) {
        #pragma unroll
        for (int nt = 0; nt < 8; nt++) {
            int r0 = bm + wm * 32 + mt * 16 + grp;
            int c0 = bn + wn * 64 + nt * 8 + 2 * thr;
            #pragma unroll
            for (int hh = 0; hh < 2; hh++) {
                int m = r0 + hh * 8;
                float v0 = acc[mt][nt][hh * 2 + 0];
                float v1 = acc[mt][nt][hh * 2 + 1];
                if (EPI >= 1) { v0 += bias[c0]; v1 += bias[c0 + 1]; }
                if (EPI == 2) {
                    v0 = 0.5f * v0 * (1.0f + erff(v0 * 0.70710678118654752f));
                    v1 = 0.5f * v1 * (1.0f + erff(v1 * 0.70710678118654752f));
                }
                if (EPI == 1) {
                    const float* rr = res + (size_t)m * N + c0;
                    v0 += rr[0]; v1 += rr[1];
                }
                if (OUTH) {
                    *(uint32_t*)((__half*)Cout + (size_t)m * N + c0) = packh2(v0, v1);
                } else {
                    *(float2*)((float*)Cout + (size_t)m * N + c0) = make_float2(v0, v1);
                }
            }
        }
    }
}

// ---------------- LayerNorm: warp per 2 rows ----------------
template <int OUTH>
__global__ __launch_bounds__(256) void ln_kernel(
    const float* __restrict__ in, const float* __restrict__ w,
    const float* __restrict__ b, void* __restrict__ out)
{
    int warp = threadIdx.x >> 5, lane = threadIdx.x & 31;
    int row0 = blockIdx.x * 16 + warp * 2;
    const float4* pa = (const float4*)(in + (size_t)row0 * DMODEL);
    const float4* pb = (const float4*)(in + (size_t)(row0 + 1) * DMODEL);

    float4 va[6], vb[6];
    float sa = 0.f, qa = 0.f, sb = 0.f, qb = 0.f;
    #pragma unroll
    for (int i = 0; i < 6; i++) {
        va[i] = pa[lane + i * 32];
        vb[i] = pb[lane + i * 32];
        sa += va[i].x + va[i].y + va[i].z + va[i].w;
        qa += va[i].x * va[i].x + va[i].y * va[i].y + va[i].z * va[i].z + va[i].w * va[i].w;
        sb += vb[i].x + vb[i].y + vb[i].z + vb[i].w;
        qb += vb[i].x * vb[i].x + vb[i].y * vb[i].y + vb[i].z * vb[i].z + vb[i].w * vb[i].w;
    }
    #pragma unroll
    for (int o = 16; o > 0; o >>= 1) {
        sa += __shfl_xor_sync(0xffffffffu, sa, o);
        qa += __shfl_xor_sync(0xffffffffu, qa, o);
        sb += __shfl_xor_sync(0xffffffffu, sb, o);
        qb += __shfl_xor_sync(0xffffffffu, qb, o);
    }
    float mua = sa * (1.0f / DMODEL), mub = sb * (1.0f / DMODEL);
    float rsa = rsqrtf(qa * (1.0f / DMODEL) - mua * mua + 1e-5f);
    float rsb = rsqrtf(qb * (1.0f / DMODEL) - mub * mub + 1e-5f);

    #pragma unroll
    for (int i = 0; i < 6; i++) {
        int c = (lane + i * 32) * 4;
        float4 wv = *(const float4*)(w + c);
        float4 bv = *(const float4*)(b + c);
        float4 ra, rb;
        ra.x = (va[i].x - mua) * rsa * wv.x + bv.x;
        ra.y = (va[i].y - mua) * rsa * wv.y + bv.y;
        ra.z = (va[i].z - mua) * rsa * wv.z + bv.z;
        ra.w = (va[i].w - mua) * rsa * wv.w + bv.w;
        rb.x = (vb[i].x - mub) * rsb * wv.x + bv.x;
        rb.y = (vb[i].y - mub) * rsb * wv.y + bv.y;
        rb.z = (vb[i].z - mub) * rsb * wv.z + bv.z;
        rb.w = (vb[i].w - mub) * rsb * wv.w + bv.w;
        if (OUTH) {
            ((uint2*)((__half*)out + (size_t)row0 * DMODEL))[lane + i * 32] =
                make_uint2(packh2(ra.x, ra.y), packh2(ra.z, ra.w));
            ((uint2*)((__half*)out + (size_t)(row0 + 1) * DMODEL))[lane + i * 32] =
                make_uint2(packh2(rb.x, rb.y), packh2(rb.z, rb.w));
        } else {
            ((float4*)((float*)out + (size_t)row0 * DMODEL))[lane + i * 32] = ra;
            ((float4*)((float*)out + (size_t)(row0 + 1) * DMODEL))[lane + i * 32] = rb;
        }
    }
}

// ---------------- fp16 tensor-core flash attention (R14-validated) ----------------
__global__ __launch_bounds__(256, 2) void attn_fp16_kernel(
    const __half* __restrict__ qkv, __half* __restrict__ out)
{
    __shared__ __half sm[18432];
    __half* Qs = sm;                     // [128][72] (staging only)
    __half* Ks = sm;                     // [64][72]
    __half* Vt = sm + 4608;              // [64][72]  transposed V: Vt[d][kk]
    __half* Ps = sm + 9216;              // [128][72]

    int tid = threadIdx.x;
    int lane = tid & 31, wid = tid >> 5;
    int grp = lane >> 2, thr = lane & 3;

    int bh = blockIdx.y;
    int b = bh / HEADS, h = bh % HEADS;
    int qt = blockIdx.x * 128;

    const __half* qbase = qkv + (size_t)(b * SEQ) * QKV3 + h * DHEAD;
    const __half* kbase = qbase + DMODEL;
    const __half* vbase = qbase + 2 * DMODEL;

    int lr = tid >> 3, lc8 = (tid & 7) * 8;
    int rot0 = tid & 7, rot1 = (tid + 256) & 7;

    uint4 kreg[2], vreg[2];
    kreg[0] = *(const uint4*)(kbase + (size_t)lr * QKV3 + lc8);
    kreg[1] = *(const uint4*)(kbase + (size_t)(lr + 32) * QKV3 + lc8);
    vreg[0] = *(const uint4*)(vbase + (size_t)lr * QKV3 + lc8);
    vreg[1] = *(const uint4*)(vbase + (size_t)(lr + 32) * QKV3 + lc8);

    {
        const __half2 s2 = __floats2half2_rn(0.125f, 0.125f);
        #pragma unroll
        for (int v = 0; v < 4; v++) {
            int idx = tid + v * 256;
            int r = idx >> 3, c8 = (idx & 7) * 8;
            uint4 q4 = *(const uint4*)(qbase + (size_t)(qt + r) * QKV3 + c8);
            __half2* hp = (__half2*)&q4;
            #pragma unroll
            for (int j = 0; j < 4; j++) hp[j] = __hmul2(hp[j], s2);
            *(uint4*)&Qs[r * 72 + c8] = q4;
        }
    }
    __syncthreads();

    uint32_t qfrag[4][4];
    int qr = wid * 16 + grp;
    #pragma unroll
    for (int ks = 0; ks < 4; ks++) {
        qfrag[ks][0] = *(const uint32_t*)&Qs[ qr      * 72 + ks * 16 + 2 * thr    ];
        qfrag[ks][1] = *(const uint32_t*)&Qs[(qr + 8) * 72 + ks * 16 + 2 * thr    ];
        qfrag[ks][2] = *(const uint32_t*)&Qs[ qr      * 72 + ks * 16 + 2 * thr + 8];
        qfrag[ks][3] = *(const uint32_t*)&Qs[(qr + 8) * 72 + ks * 16 + 2 * thr + 8];
    }
    __syncthreads();

    float acc_o[8][4];
    #pragma unroll
    for (int nt = 0; nt < 8; nt++)
        #pragma unroll
        for (int v = 0; v < 4; v++) acc_o[nt][v] = 0.f;
    float m0 = -1e30f, m1 = -1e30f, l0 = 0.f, l1 = 0.f;

    for (int kt0 = 0; kt0 < SEQ; kt0 += 64) {
        {
            *(uint4*)&Ks[lr * 72 + lc8] = kreg[0];
            *(uint4*)&Ks[(lr + 32) * 72 + lc8] = kreg[1];
            const __half* vh0 = (const __half*)&vreg[0];
            const __half* vh1 = (const __half*)&vreg[1];
            #pragma unroll
            for (int j = 0; j < 8; j++) {
                int j0 = (j + rot0) & 7;
                Vt[(lc8 + j0) * 72 + lr] = vh0[j0];
                int j1 = (j + rot1) & 7;
                Vt[(lc8 + j1) * 72 + lr + 32] = vh1[j1];
            }
        }
        __syncthreads();

        if (kt0 + 64 < SEQ) {
            const __half* kp = kbase + (size_t)(kt0 + 64) * QKV3;
            const __half* vp = vbase + (size_t)(kt0 + 64) * QKV3;
            kreg[0] = *(const uint4*)(kp + (size_t)lr * QKV3 + lc8);
            kreg[1] = *(const uint4*)(kp + (size_t)(lr + 32) * QKV3 + lc8);
            vreg[0] = *(const uint4*)(vp + (size_t)lr * QKV3 + lc8);
            vreg[1] = *(const uint4*)(vp + (size_t)(lr + 32) * QKV3 + lc8);
        }

        float acc_s[8][4];
        #pragma unroll
        for (int nt = 0; nt < 8; nt++)
            #pragma unroll
            for (int v = 0; v < 4; v++) acc_s[nt][v] = 0.f;

        #pragma unroll
        for (int ks = 0; ks < 4; ks++) {
            #pragma unroll
            for (int nt = 0; nt < 8; nt++) {
                int c = nt * 8 + grp;
                uint32_t b0 = *(const uint32_t*)&Ks[c * 72 + ks * 16 + 2 * thr    ];
                uint32_t b1 = *(const uint32_t*)&Ks[c * 72 + ks * 16 + 2 * thr + 8];
                mma_f16_16x8x16(acc_s[nt], qfrag[ks], b0, b1);
            }
        }

        float tm0 = -1e30f, tm1 = -1e30f;
        #pragma unroll
        for (int nt = 0; nt < 8; nt++) {
            tm0 = fmaxf(tm0, fmaxf(acc_s[nt][0], acc_s[nt][1]));
            tm1 = fmaxf(tm1, fmaxf(acc_s[nt][2], acc_s[nt][3]));
        }
        tm0 = fmaxf(tm0, __shfl_xor_sync(0xffffffffu, tm0, 1));
        tm0 = fmaxf(tm0, __shfl_xor_sync(0xffffffffu, tm0, 2));
        tm1 = fmaxf(tm1, __shfl_xor_sync(0xffffffffu, tm1, 1));
        tm1 = fmaxf(tm1, __shfl_xor_sync(0xffffffffu, tm1, 2));

        float nm0 = fmaxf(m0, tm0), nm1 = fmaxf(m1, tm1);
        float c0 = __expf(m0 - nm0),  c1 = __expf(m1 - nm1);

        float s0 = 0.f, s1 = 0.f;
        #pragma unroll
        for (int nt = 0; nt < 8; nt++) {
            acc_s[nt][0] = __expf(acc_s[nt][0] - nm0);
            acc_s[nt][1] = __expf(acc_s[nt][1] - nm0);
            acc_s[nt][2] = __expf(acc_s[nt][2] - nm1);
            acc_s[nt][3] = __expf(acc_s[nt][3] - nm1);
            s0 += acc_s[nt][0] + acc_s[nt][1];
            s1 += acc_s[nt][2] + acc_s[nt][3];
        }
        s0 += __shfl_xor_sync(0xffffffffu, s0, 1);
        s0 += __shfl_xor_sync(0xffffffffu, s0, 2);
        s1 += __shfl_xor_sync(0xffffffffu, s1, 1);
        s1 += __shfl_xor_sync(0xffffffffu, s1, 2);

        l0 = l0 * c0 + s0;  l1 = l1 * c1 + s1;
        m0 = nm0;           m1 = nm1;

        #pragma unroll
        for (int nt = 0; nt < 8; nt++) {
            acc_o[nt][0] *= c0; acc_o[nt][1] *= c0;
            acc_o[nt][2] *= c1; acc_o[nt][3] *= c1;
        }

        #pragma unroll
        for (int nt = 0; nt < 8; nt++) {
            *(uint32_t*)&Ps[ qr      * 72 + nt * 8 + 2 * thr] = packh2(acc_s[nt][0], acc_s[nt][1]);
            *(uint32_t*)&Ps[(qr + 8) * 72 + nt * 8 + 2 * thr] = packh2(acc_s[nt][2], acc_s[nt][3]);
        }
        __syncwarp();

        #pragma unroll
        for (int ks2 = 0; ks2 < 4; ks2++) {
            uint32_t af[4];
            af[0] = *(const uint32_t*)&Ps[ qr      * 72 + ks2 * 16 + 2 * thr    ];
            af[1] = *(const uint32_t*)&Ps[(qr + 8) * 72 + ks2 * 16 + 2 * thr    ];
            af[2] = *(const uint32_t*)&Ps[ qr      * 72 + ks2 * 16 + 2 * thr + 8];
            af[3] = *(const uint32_t*)&Ps[(qr + 8) * 72 + ks2 * 16 + 2 * thr + 8];
            #pragma unroll
            for (int nt = 0; nt < 8; nt++) {
                int d = nt * 8 + grp;
                uint32_t b0 = *(const uint32_t*)&Vt[d * 72 + ks2 * 16 + 2 * thr    ];
                uint32_t b1 = *(const uint32_t*)&Vt[d * 72 + ks2 * 16 + 2 * thr + 8];
                mma_f16_16x8x16(acc_o[nt], af, b0, b1);
            }
        }
        __syncthreads();
    }

    float il0 = 1.0f / l0, il1 = 1.0f / l1;
    int tok0 = b * SEQ + qt + wid * 16 + grp;
    #pragma unroll
    for (int nt = 0; nt < 8; nt++) {
        int col = h * DHEAD + nt * 8 + 2 * thr;
        *(uint32_t*)(out + (size_t)tok0 * DMODEL + col) =
            packh2(acc_o[nt][0] * il0, acc_o[nt][1] * il0);
        *(uint32_t*)(out + (size_t)(tok0 + 8) * DMODEL + col) =
            packh2(acc_o[nt][2] * il1, acc_o[nt][3] * il1);
    }
}

// ---------------- host orchestration ----------------
extern "C" void kernel_launch(void* const* d_in, const int* in_sizes, int n_in,
                              void* d_out, int out_size)
{
    const float* x     = (const float*)d_in[0];
    const float* ln1w  = (const float*)d_in[1];
    const float* ln1b  = (const float*)d_in[2];
    const float* wqkv  = (const float*)d_in[3];
    const float* wo    = (const float*)d_in[4];
    const float* bo    = (const float*)d_in[5];
    const float* ln2w  = (const float*)d_in[6];
    const float* ln2b  = (const float*)d_in[7];
    const float* w1    = (const float*)d_in[8];
    const float* b1    = (const float*)d_in[9];
    const float* w2    = (const float*)d_in[10];
    const float* b2    = (const float*)d_in[11];
    const float* lnfw  = (const float*)d_in[12];
    const float* lnfb  = (const float*)d_in[13];

    float *gx;
    __half *gh, *gqkv, *gao, *gff;
    cudaGetSymbolAddress((void**)&gx,   g_x);
    cudaGetSymbolAddress((void**)&gh,   g_h);
    cudaGetSymbolAddress((void**)&gqkv, g_qkv);
    cudaGetSymbolAddress((void**)&gao,  g_attnout);
    cudaGetSymbolAddress((void**)&gff,  g_ff);

    __half *qkvT, *woT, *w1T, *w2T;
    cudaGetSymbolAddress((void**)&qkvT, g_wqkvT);
    cudaGetSymbolAddress((void**)&woT,  g_woT);
    cudaGetSymbolAddress((void**)&w1T,  g_w1T);
    cudaGetSymbolAddress((void**)&w2T,  g_w2T);

    // ---- weight transpose prepass ----
    wtrans_kernel<<<dim3(DMODEL / 32, QKV3 / 32, DEPTH), 256>>>(wqkv, qkvT, DMODEL, QKV3);
    wtrans_kernel<<<dim3(DMODEL / 32, DMODEL / 32, DEPTH), 256>>>(wo, woT, DMODEL, DMODEL);
    wtrans_kernel<<<dim3(DMODEL / 32, DFF / 32, DEPTH), 256>>>(w1, w1T, DMODEL, DFF);
    wtrans_kernel<<<dim3(DFF / 32, DMODEL / 32, DEPTH), 256>>>(w2, w2T, DFF, DMODEL);

    for (int l = 0; l < DEPTH; l++) {
        const float* L1w = ln1w + (size_t)l * DMODEL;
        const float* L1b = ln1b + (size_t)l * DMODEL;
        const float* Bo  = bo   + (size_t)l * DMODEL;
        const float* L2w = ln2w + (size_t)l * DMODEL;
        const float* L2b = ln2b + (size_t)l * DMODEL;
        const float* B1  = b1   + (size_t)l * DFF;
        const float* B2  = b2   + (size_t)l * DMODEL;

        const __half* Wq = qkvT + (size_t)l * QKV3 * DMODEL;
        const __half* Wo = woT  + (size_t)l * DMODEL * DMODEL;
        const __half* W1 = w1T  + (size_t)l * DFF * DMODEL;
        const __half* W2 = w2T  + (size_t)l * DMODEL * DFF;

        // layer 0 reads the residual stream from the harness input directly;
        // g_x is first WRITTEN by layer 0's O-proj (copy kernel eliminated).
        const float* xin = (l == 0) ? x : gx;

        ln_kernel<1><<<TOKENS / 16, 256>>>(xin, L1w, L1b, gh);
        gemm_fp16_kernel<0, 1><<<dim3(QKV3 / 128, TOKENS / 128), 256>>>(
            gh, Wq, nullptr, nullptr, gqkv, TOKENS, QKV3, DMODEL);
        attn_fp16_kernel<<<dim3(SEQ / 128, 8 * HEADS), 256>>>(gqkv, gao);
        gemm_fp16_kernel<1, 0><<<dim3(DMODEL / 128, TOKENS / 128), 256>>>(
            gao, Wo, Bo, xin, gx, TOKENS, DMODEL, DMODEL);
        ln_kernel<1><<<TOKENS / 16, 256>>>(gx, L2w, L2b, gh);
        gemm_fp16_kernel<2, 1><<<dim3(DFF / 128, TOKENS / 128), 256>>>(
            gh, W1, B1, nullptr, gff, TOKENS, DFF, DMODEL);
        gemm_fp16_kernel<1, 0><<<dim3(DMODEL / 128, TOKENS / 128), 256>>>(
            gff, W2, B2, gx, gx, TOKENS, DMODEL, DFF);
    }

    ln_kernel<0><<<TOKENS / 16, 256>>>(gx, lnfw, lnfb, (float*)d_out);
}